// round 16
// baseline (speedup 1.0000x reference)
#include <cuda_runtime.h>
#include <cuda_fp16.h>
#include <cstdint>
#include <cstddef>

// ---------------------------------------------------------------------------
// Dimensions: B=4, H=W=8, M=16, C=256, NH=8, HD=32, GW=2
// ---------------------------------------------------------------------------
#define T0      65536
#define T1      4096
#define NWIN0   256
#define NWIN1   16

#define TILE_BYTES 16384
#define BUF_BYTES  (2 * TILE_BYTES)
#define GEMM_SMEM  (3 * BUF_BYTES)

#define ATTN_ROWB  80
#define ATTN_SMEM  (3 * 256 * ATTN_ROWB)

// ---------------------------------------------------------------------------
// PTX helpers
// ---------------------------------------------------------------------------
__device__ __forceinline__ uint32_t smem_u32(const void* p) {
    uint32_t a;
    asm("{ .reg .u64 t; cvta.to.shared.u64 t, %1; cvt.u32.u64 %0, t; }" : "=r"(a) : "l"(p));
    return a;
}
__device__ __forceinline__ void cp16(uint32_t dst, const void* src) {
    asm volatile("cp.async.cg.shared.global [%0], [%1], 16;" :: "r"(dst), "l"(src) : "memory");
}
#define CP_COMMIT() asm volatile("cp.async.commit_group;" ::: "memory")
#define CP_WAIT2()  asm volatile("cp.async.wait_group 2;" ::: "memory")
#define CP_WAIT1()  asm volatile("cp.async.wait_group 1;" ::: "memory")
#define CP_WAIT0()  asm volatile("cp.async.wait_group 0;" ::: "memory")

__device__ __forceinline__ void ldsm4(uint32_t& r0, uint32_t& r1, uint32_t& r2,
                                      uint32_t& r3, uint32_t addr) {
    asm volatile("ldmatrix.sync.aligned.m8n8.x4.shared.b16 {%0,%1,%2,%3}, [%4];"
                 : "=r"(r0), "=r"(r1), "=r"(r2), "=r"(r3) : "r"(addr));
}
__device__ __forceinline__ void ldsm4t(uint32_t& r0, uint32_t& r1, uint32_t& r2,
                                       uint32_t& r3, uint32_t addr) {
    asm volatile("ldmatrix.sync.aligned.m8n8.x4.trans.shared.b16 {%0,%1,%2,%3}, [%4];"
                 : "=r"(r0), "=r"(r1), "=r"(r2), "=r"(r3) : "r"(addr));
}
__device__ __forceinline__ void mma16816(float* c, const uint32_t* a, const uint32_t* b) {
    asm volatile(
        "mma.sync.aligned.m16n8k16.row.col.f32.f16.f16.f32 "
        "{%0,%1,%2,%3}, {%4,%5,%6,%7}, {%8,%9}, {%0,%1,%2,%3};"
        : "+f"(c[0]), "+f"(c[1]), "+f"(c[2]), "+f"(c[3])
        : "r"(a[0]), "r"(a[1]), "r"(a[2]), "r"(a[3]), "r"(b[0]), "r"(b[1]));
}
__device__ __forceinline__ uint32_t packh2(float a, float b) {
    __half2 h = __floats2half2_rn(a, b);
    return *(uint32_t*)&h;
}
__device__ __forceinline__ float2 unpackh2(uint32_t u) {
    return __half22float2(*(__half2*)&u);
}

// Row-level permutation: gidx -> o1-row
__device__ __forceinline__ int scatter_perm(int g) {
    int rr = g & 15, r1 = rr >> 2, r2 = rr & 3;
    int bhw = g >> 4;
    int w = bhw & 7, h = (bhw >> 3) & 7, b = bhw >> 6;
    int R = h * 4 + r1, Cc = w * 4 + r2;
    return (((b * 2 + (R >> 4)) * 2 + (Cc >> 4)) << 8) + (R & 15) * 16 + (Cc & 15);
}

// ---------------------------------------------------------------------------
// Scratch
// ---------------------------------------------------------------------------
__device__ float g_PE [2 * 256 * 256];
__device__ __half g_X0h[(size_t)T0 * 256];
__device__ __half g_X1h[(size_t)T1 * 256];
__device__ __half g_Gh [(size_t)T1 * 256];
__device__ __half g_Qbh[(size_t)T1 * 256];
__device__ __half g_QKVh[(size_t)T0 * 768];   // QKV; then o0h copy; then KV
__device__ __half g_QKVc[(size_t)T1 * 768];
__device__ __half g_A  [(size_t)T0 * 256];
__device__ __half g_Ac [(size_t)T1 * 256];
__device__ __half g_H1 [(size_t)T0 * 1024];
__device__ __half g_H1c[(size_t)T1 * 1024];
__device__ __half g_A3 [(size_t)T1 * 256];
__device__ __half g_WqkvT[2 * 768 * 256];
__device__ __half g_WoT  [2 * 256 * 256];
__device__ __half g_W1T  [2 * 1024 * 256];
__device__ __half g_W2T  [2 * 256 * 1024];

// ---------------------------------------------------------------------------
// Elementwise helpers: contiguous 8 channels per lane
// ---------------------------------------------------------------------------
__device__ __forceinline__ void load8h(const __half* row, int lane,
                                       float4& v0, float4& v1) {
    uint4 u = ((const uint4*)row)[lane];
    float2 f0 = unpackh2(u.x), f1 = unpackh2(u.y);
    float2 f2 = unpackh2(u.z), f3 = unpackh2(u.w);
    v0 = make_float4(f0.x, f0.y, f1.x, f1.y);
    v1 = make_float4(f2.x, f2.y, f3.x, f3.y);
}
__device__ __forceinline__ void store8h(__half* row, int lane, float4 v0, float4 v1) {
    uint4 u;
    u.x = packh2(v0.x, v0.y); u.y = packh2(v0.z, v0.w);
    u.z = packh2(v1.x, v1.y); u.w = packh2(v1.z, v1.w);
    ((uint4*)row)[lane] = u;
}
__device__ __forceinline__ void ln_store8(float4 v0, float4 v1, int lane,
                                          const float* __restrict__ gamma,
                                          const float* __restrict__ beta,
                                          __half* __restrict__ orow) {
    float s = v0.x + v0.y + v0.z + v0.w + v1.x + v1.y + v1.z + v1.w;
#pragma unroll
    for (int d = 16; d; d >>= 1) s += __shfl_xor_sync(0xffffffffu, s, d);
    float mean = s * (1.f / 256.f);
    float d0x = v0.x - mean, d0y = v0.y - mean, d0z = v0.z - mean, d0w = v0.w - mean;
    float d1x = v1.x - mean, d1y = v1.y - mean, d1z = v1.z - mean, d1w = v1.w - mean;
    float q = d0x*d0x + d0y*d0y + d0z*d0z + d0w*d0w +
              d1x*d1x + d1y*d1y + d1z*d1z + d1w*d1w;
#pragma unroll
    for (int d = 16; d; d >>= 1) q += __shfl_xor_sync(0xffffffffu, q, d);
    float rstd = rsqrtf(q * (1.f / 256.f) + 1e-5f);
    float4 g0 = ((const float4*)gamma)[2 * lane], g1 = ((const float4*)gamma)[2 * lane + 1];
    float4 b0 = ((const float4*)beta)[2 * lane],  b1 = ((const float4*)beta)[2 * lane + 1];
    uint4 u;
    u.x = packh2(fmaf(d0x * rstd, g0.x, b0.x), fmaf(d0y * rstd, g0.y, b0.y));
    u.y = packh2(fmaf(d0z * rstd, g0.z, b0.z), fmaf(d0w * rstd, g0.w, b0.w));
    u.z = packh2(fmaf(d1x * rstd, g1.x, b1.x), fmaf(d1y * rstd, g1.y, b1.y));
    u.w = packh2(fmaf(d1z * rstd, g1.z, b1.z), fmaf(d1w * rstd, g1.w, b1.w));
    ((uint4*)orow)[lane] = u;
}

// ---------------------------------------------------------------------------
// Small kernels
// ---------------------------------------------------------------------------
__global__ void posemb_kernel(const float* __restrict__ pe_w1,
                              const float* __restrict__ pe_b1,
                              const float* __restrict__ pe_w2,
                              float* __restrict__ PE) {
    int s = blockIdx.x >> 8;
    int n = blockIdx.x & 255;
    int i = n >> 4, j = n & 15;
    float cy = (i - 8) * 0.125f;
    float cx = (j - 8) * 0.125f;
    __shared__ float hid[512];
    const float* w1 = pe_w1 + s * 2 * 512;
    const float* b1 = pe_b1 + s * 512;
    for (int k = threadIdx.x; k < 512; k += 256)
        hid[k] = fmaxf(0.f, fmaf(cy, w1[k], fmaf(cx, w1[512 + k], b1[k])));
    __syncthreads();
    const float* w2 = pe_w2 + (size_t)s * 512 * 256;
    int c = threadIdx.x;
    float acc = 0.f;
#pragma unroll 8
    for (int k = 0; k < 512; k++) acc = fmaf(hid[k], w2[(size_t)k * 256 + c], acc);
    PE[((size_t)s * 256 + n) * 256 + c] = acc;
}

__global__ void __launch_bounds__(256)
add_pe0_ln_kernel(const float* __restrict__ s0, const float* __restrict__ PE,
                  __half* __restrict__ X0h, __half* __restrict__ A,
                  const float* __restrict__ gamma, const float* __restrict__ beta) {
    int token = blockIdx.x * 8 + (threadIdx.x >> 5);
    int lane = threadIdx.x & 31;
    const float4* sr = (const float4*)(s0 + (size_t)token * 256);
    const float4* pr = (const float4*)(PE + (size_t)(token & 255) * 256);
    float4 v0 = sr[2 * lane], v1 = sr[2 * lane + 1];
    float4 p0 = pr[2 * lane], p1 = pr[2 * lane + 1];
    v0.x += p0.x; v0.y += p0.y; v0.z += p0.z; v0.w += p0.w;
    v1.x += p1.x; v1.y += p1.y; v1.z += p1.z; v1.w += p1.w;
    store8h(X0h + (size_t)token * 256, lane, v0, v1);
    ln_store8(v0, v1, lane, gamma, beta, A + (size_t)token * 256);
}

__global__ void __launch_bounds__(256)
pool_add_ln_kernel(const float* __restrict__ s1, const float* __restrict__ PE,
                   const __half* __restrict__ X0h, __half* __restrict__ X1h,
                   __half* __restrict__ Ac,
                   const float* __restrict__ gamma, const float* __restrict__ beta) {
    int token = blockIdx.x * 8 + (threadIdx.x >> 5);
    int lane = threadIdx.x & 31;
    int t  = token & 255;
    int gw = token >> 8;
    int b = gw >> 2, gi = (gw >> 1) & 1, gj = gw & 1;
    int ti = t >> 4, tj = t & 15;
    int R  = gi * 16 + ti, Cc = gj * 16 + tj;
    int h = R >> 2, r1 = R & 3, w = Cc >> 2, r2 = Cc & 3;
    int fw = b * 64 + h * 8 + w;
    float4 m0 = make_float4(-1e30f, -1e30f, -1e30f, -1e30f), m1 = m0;
#pragma unroll
    for (int p1 = 0; p1 < 4; p1++)
#pragma unroll
        for (int p2 = 0; p2 < 4; p2++) {
            int n = (r1 * 4 + p1) * 16 + r2 * 4 + p2;
            float4 a, c;
            load8h(X0h + ((size_t)fw * 256 + n) * 256, lane, a, c);
            m0.x = fmaxf(m0.x, a.x); m0.y = fmaxf(m0.y, a.y);
            m0.z = fmaxf(m0.z, a.z); m0.w = fmaxf(m0.w, a.w);
            m1.x = fmaxf(m1.x, c.x); m1.y = fmaxf(m1.y, c.y);
            m1.z = fmaxf(m1.z, c.z); m1.w = fmaxf(m1.w, c.w);
        }
    const float4* sr = (const float4*)(s1 + (size_t)token * 256);
    const float4* pr = (const float4*)(PE + (size_t)(256 + t) * 256);
    float4 s0v = sr[2 * lane], s1v = sr[2 * lane + 1];
    float4 p0 = pr[2 * lane], p1v = pr[2 * lane + 1];
    m0.x += s0v.x + p0.x; m0.y += s0v.y + p0.y;
    m0.z += s0v.z + p0.z; m0.w += s0v.w + p0.w;
    m1.x += s1v.x + p1v.x; m1.y += s1v.y + p1v.y;
    m1.z += s1v.z + p1v.z; m1.w += s1v.w + p1v.w;
    store8h(X1h + (size_t)token * 256, lane, m0, m1);
    ln_store8(m0, m1, lane, gamma, beta, Ac + (size_t)token * 256);
}

__global__ void __launch_bounds__(256)
ln_half_h_kernel(const __half* __restrict__ x, __half* __restrict__ o,
                 const float* __restrict__ gamma, const float* __restrict__ beta,
                 const __half* __restrict__ x2, __half* __restrict__ o2,
                 const float* __restrict__ gamma2, const float* __restrict__ beta2,
                 int split) {
    int blk = blockIdx.x;
    const __half* xp = x; __half* op = o;
    const float* gp = gamma; const float* bp = beta;
    if (blk >= split) { blk -= split; xp = x2; op = o2; gp = gamma2; bp = beta2; }
    int token = blk * 8 + (threadIdx.x >> 5);
    int lane = threadIdx.x & 31;
    float4 v0, v1;
    load8h(xp + (size_t)token * 256, lane, v0, v1);
    ln_store8(v0, v1, lane, gp, bp, op + (size_t)token * 256);
}

// Combined pre-cross LN; fine part reads fp16 o0 copy (o0h).
__global__ void __launch_bounds__(256)
ln_pre_cross_kernel(const __half* __restrict__ o0h, __half* __restrict__ Afine,
                    const __half* __restrict__ X1h, __half* __restrict__ Gh,
                    __half* __restrict__ A3,
                    const float* __restrict__ gamma, const float* __restrict__ beta,
                    int split) {
    int blk = blockIdx.x;
    int lane = threadIdx.x & 31;
    if (blk < split) {
        int fidx = blk * 8 + (threadIdx.x >> 5);
        int pp = fidx & 15, p1 = pp >> 2, p2 = pp & 3;
        int grp = fidx >> 4;
        int rr = grp & 15, r1 = rr >> 2, r2 = rr & 3;
        int bhw = grp >> 4;
        int w = bhw & 7, h = (bhw >> 3) & 7, b = bhw >> 6;
        int fw = b * 64 + h * 8 + w;
        int n = (r1 * 4 + p1) * 16 + r2 * 4 + p2;
        float4 v0, v1;
        load8h(o0h + ((size_t)fw * 256 + n) * 256, lane, v0, v1);
        ln_store8(v0, v1, lane, gamma, beta, Afine + (size_t)fidx * 256);
    } else {
        int gidx = (blk - split) * 8 + (threadIdx.x >> 5);
        int rr = gidx & 15, r1 = rr >> 2, r2 = rr & 3;
        int bhw = gidx >> 4;
        int w = bhw & 7, h = (bhw >> 3) & 7, b = bhw >> 6;
        int R = h * 4 + r1, Cc = w * 4 + r2;
        int gi = R >> 4, ti = R & 15, gj = Cc >> 4, tj = Cc & 15;
        int win = (b * 2 + gi) * 2 + gj, tok = ti * 16 + tj;
        const __half* src = X1h + ((size_t)win * 256 + tok) * 256;
        uint4 raw = ((const uint4*)src)[lane];
        ((uint4*)(Gh + (size_t)gidx * 256))[lane] = raw;
        float4 v0, v1;
        load8h(src, lane, v0, v1);
        ln_store8(v0, v1, lane, gamma, beta, A3 + (size_t)gidx * 256);
    }
}

// Coalesced weight transpose-convert: W[K,N] fp32 -> T[N,K] fp16 (64x64 tiles)
__global__ void __launch_bounds__(256)
wconv_all_kernel(const float* __restrict__ wqkv, const float* __restrict__ wo,
                 const float* __restrict__ mw1, const float* __restrict__ mw2,
                 __half* __restrict__ Tqkv, __half* __restrict__ To,
                 __half* __restrict__ Tm1,  __half* __restrict__ Tm2) {
    __shared__ float sm[64][65];
    int bid = blockIdx.x;
    int s = bid / 192, r = bid % 192;
    const float* W; __half* T; int K, N, tk, tn;
    if (r < 48)      { W = wqkv + (size_t)s * 196608; T = Tqkv + (size_t)s * 196608;
                       K = 256;  N = 768;  tk = r % 4;          tn = r / 4; }
    else if (r < 64) { W = wo   + (size_t)s * 65536;  T = To   + (size_t)s * 65536;
                       K = 256;  N = 256;  tk = (r - 48) % 4;   tn = (r - 48) / 4; }
    else if (r < 128){ W = mw1  + (size_t)s * 262144; T = Tm1  + (size_t)s * 262144;
                       K = 256;  N = 1024; tk = (r - 64) % 4;   tn = (r - 64) / 4; }
    else             { W = mw2  + (size_t)s * 262144; T = Tm2  + (size_t)s * 262144;
                       K = 1024; N = 256;  tk = (r - 128) % 16; tn = (r - 128) / 16; }
    int k0 = tk * 64, n0 = tn * 64;
    int c = threadIdx.x & 63, rr = threadIdx.x >> 6;
#pragma unroll
    for (int i = 0; i < 16; i++) {
        int krow = rr + i * 4;
        sm[krow][c] = W[(size_t)(k0 + krow) * N + n0 + c];
    }
    __syncthreads();
#pragma unroll
    for (int i = 0; i < 16; i++) {
        int nrow = rr + i * 4;
        T[(size_t)(n0 + nrow) * K + k0 + c] = __float2half(sm[c][nrow]);
    }
}

// ---------------------------------------------------------------------------
// fp16 1-pass GEMM, dual-problem, runtime epilogue code per problem.
// epi 1: GELU -> Oh.  2: +resH -> Cp fp32.  3: -> Oh fp16 (row-major).
// epi 4: +resH -> Cp fp32 @ scatter_perm.  5: +resH -> Oh fp16.
// epi 6: +resH -> Cp fp32 AND Oh fp16.
// ---------------------------------------------------------------------------
__global__ void __launch_bounds__(256)
gemm_mma(const __half* A, const __half* B,
         const float* bias, const __half* resH,
         float* Cp, __half* Oh, int epiA,
         const __half* A2, const __half* B2,
         const float* bias2, const __half* resH2,
         float* Cp2, __half* Oh2, int epiB,
         int bmSplit, int K, int ldc, int ldc2, int bn2Max) {
    extern __shared__ char smc[];
    const uint32_t sb = smem_u32(smc);
    int tid = threadIdx.x, lane = tid & 31, wid = tid >> 5;
    int wm = wid >> 2, wn = wid & 3;
    int bm = blockIdx.y, bn = blockIdx.x;
    int epi = epiA;
    if (bm >= bmSplit) {
        bm -= bmSplit;
        if (bn >= bn2Max) return;
        A = A2; B = B2; bias = bias2; resH = resH2; Cp = Cp2; Oh = Oh2;
        ldc = ldc2; epi = epiB;
    }

    const __half* src0 = A + (size_t)bm * 128 * K;
    const __half* src1 = B + (size_t)bn * 128 * K;

    int nc = K >> 6;
    int crow0 = tid >> 3, ccol = tid & 7;

#define PREFETCH(CH, BUF) do {                                                 \
    int _k0 = (CH) << 6;                                                       \
    const __half* _s[2] = {src0 + _k0, src1 + _k0};                            \
    _Pragma("unroll")                                                          \
    for (int _op = 0; _op < 2; _op++) {                                        \
        uint32_t _db = sb + (BUF) * BUF_BYTES + _op * TILE_BYTES;              \
        _Pragma("unroll")                                                      \
        for (int _i = 0; _i < 4; _i++) {                                       \
            int _row = crow0 + _i * 32;                                        \
            uint32_t _doff = _db + _row * 128 + ((ccol ^ (_row & 7)) << 4);    \
            cp16(_doff, _s[_op] + (size_t)_row * K + ccol * 8);                \
        }                                                                      \
    }                                                                          \
} while (0)

    float acc[4][4][4];
#pragma unroll
    for (int mi = 0; mi < 4; mi++)
#pragma unroll
        for (int ni = 0; ni < 4; ni++)
#pragma unroll
            for (int r = 0; r < 4; r++) acc[mi][ni][r] = 0.f;

    PREFETCH(0, 0);
    CP_COMMIT();
    if (nc > 1) { PREFETCH(1, 1); CP_COMMIT(); }

    int a_rl = lane & 15;
    int b_rl = ((lane >> 4) << 3) + (lane & 7);

    for (int ch = 0; ch < nc; ch++) {
        int buf = ch % 3;
        if (ch + 2 < nc) {
            PREFETCH(ch + 2, (ch + 2) % 3);
            CP_COMMIT();
            CP_WAIT2();
        } else if (ch + 1 < nc) {
            CP_WAIT1();
        } else {
            CP_WAIT0();
        }
        __syncthreads();

        uint32_t base = sb + buf * BUF_BYTES;
#pragma unroll
        for (int ks = 0; ks < 4; ks++) {
            uint32_t ah[4][4], bh[4][2];
            int achunk = ks * 2 + (lane >> 4);
            int bchunk = ks * 2 + ((lane >> 3) & 1);
#pragma unroll
            for (int mi = 0; mi < 4; mi++) {
                int row = wm * 64 + mi * 16 + a_rl;
                uint32_t off = (uint32_t)(row * 128 + ((achunk ^ (row & 7)) << 4));
                ldsm4(ah[mi][0], ah[mi][1], ah[mi][2], ah[mi][3], base + off);
            }
#pragma unroll
            for (int np = 0; np < 2; np++) {
                int row = wn * 32 + np * 16 + b_rl;
                uint32_t off = (uint32_t)(row * 128 + ((bchunk ^ (row & 7)) << 4));
                uint32_t r0, r1, r2, r3;
                ldsm4(r0, r1, r2, r3, base + TILE_BYTES + off);
                bh[np * 2][0] = r0; bh[np * 2][1] = r1;
                bh[np * 2 + 1][0] = r2; bh[np * 2 + 1][1] = r3;
            }
#pragma unroll
            for (int mi = 0; mi < 4; mi++)
#pragma unroll
                for (int ni = 0; ni < 4; ni++)
                    mma16816(acc[mi][ni], ah[mi], bh[ni]);
        }
        __syncthreads();
    }
#undef PREFETCH

    int l4 = lane >> 2, l2 = (lane & 3) << 1;
#pragma unroll
    for (int mi = 0; mi < 4; mi++) {
        int r0 = bm * 128 + wm * 64 + mi * 16 + l4;
        int sr0 = (epi == 4) ? scatter_perm(r0) : r0;
        int sr1 = (epi == 4) ? scatter_perm(r0 + 8) : r0 + 8;
#pragma unroll
        for (int ni = 0; ni < 4; ni++) {
            int cc = bn * 128 + wn * 32 + ni * 8 + l2;
            float b0 = bias[cc], b1 = bias[cc + 1];
            float v00 = acc[mi][ni][0] + b0, v01 = acc[mi][ni][1] + b1;
            float v10 = acc[mi][ni][2] + b0, v11 = acc[mi][ni][3] + b1;
            size_t o0 = (size_t)r0 * ldc + cc;
            size_t o1 = (size_t)(r0 + 8) * ldc + cc;
            if (epi == 1) {
                const float is2 = 0.7071067811865476f;
                float g00 = 0.5f * v00 * (1.f + erff(v00 * is2));
                float g01 = 0.5f * v01 * (1.f + erff(v01 * is2));
                float g10 = 0.5f * v10 * (1.f + erff(v10 * is2));
                float g11 = 0.5f * v11 * (1.f + erff(v11 * is2));
                *(uint32_t*)(Oh + o0) = packh2(g00, g01);
                *(uint32_t*)(Oh + o1) = packh2(g10, g11);
            } else if (epi == 3) {
                *(uint32_t*)(Oh + o0) = packh2(v00, v01);
                *(uint32_t*)(Oh + o1) = packh2(v10, v11);
            } else {
                float2 ra = unpackh2(*(const uint32_t*)(resH + o0));
                float2 rb = unpackh2(*(const uint32_t*)(resH + o1));
                v00 += ra.x; v01 += ra.y; v10 += rb.x; v11 += rb.y;
                if (epi == 5) {
                    *(uint32_t*)(Oh + o0) = packh2(v00, v01);
                    *(uint32_t*)(Oh + o1) = packh2(v10, v11);
                } else {
                    *(float2*)(Cp + (size_t)sr0 * ldc + cc) = make_float2(v00, v01);
                    *(float2*)(Cp + (size_t)sr1 * ldc + cc) = make_float2(v10, v11);
                    if (epi == 6) {
                        *(uint32_t*)(Oh + o0) = packh2(v00, v01);
                        *(uint32_t*)(Oh + o1) = packh2(v10, v11);
                    }
                }
            }
        }
    }
}

// ---------------------------------------------------------------------------
// Tensor-core flash attention (no-max softmax), dual-problem.
// QKV input row-major [T, 768] (Q | K | V each 256 halves).
// ---------------------------------------------------------------------------
__global__ void __launch_bounds__(256)
attn_mma_kernel(const __half* qkv, __half* out,
                const __half* qkv2, __half* out2, int ctaSplit) {
    extern __shared__ char smc[];
    const uint32_t sb = smem_u32(smc);
    const uint32_t sbQ = sb, sbK = sb + 256 * ATTN_ROWB, sbV = sb + 512 * ATTN_ROWB;
    int cta = blockIdx.x;
    if (cta >= ctaSplit) { cta -= ctaSplit; qkv = qkv2; out = out2; }
    int win = cta >> 3, head = cta & 7;
    int tid = threadIdx.x, lane = tid & 31, wid = tid >> 5;

    {
        const uint4* src = (const uint4*)(qkv + ((size_t)(win * 256 + tid) * 768 + head * 32));
        uint4* dq = (uint4*)(smc + tid * ATTN_ROWB);
        uint4* dk = (uint4*)(smc + 256 * ATTN_ROWB + tid * ATTN_ROWB);
        uint4* dv = (uint4*)(smc + 512 * ATTN_ROWB + tid * ATTN_ROWB);
#pragma unroll
        for (int c = 0; c < 4; c++) dq[c] = src[c];
#pragma unroll
        for (int c = 0; c < 4; c++) dk[c] = src[32 + c];
#pragma unroll
        for (int c = 0; c < 4; c++) dv[c] = src[64 + c];
    }
    __syncthreads();

    uint32_t aq[2][2][4];
#pragma unroll
    for (int mi = 0; mi < 2; mi++)
#pragma unroll
        for (int kt = 0; kt < 2; kt++) {
            int row = wid * 32 + mi * 16 + (lane & 15);
            uint32_t addr = sbQ + row * ATTN_ROWB + (kt * 2 + (lane >> 4)) * 16;
            ldsm4(aq[mi][kt][0], aq[mi][kt][1], aq[mi][kt][2], aq[mi][kt][3], addr);
        }

    float o[2][4][4];
#pragma unroll
    for (int mi = 0; mi < 2; mi++)
#pragma unroll
        for (int ni = 0; ni < 4; ni++)
#pragma unroll
            for (int r = 0; r < 4; r++) o[mi][ni][r] = 0.f;
    float l[2][2] = {{0.f, 0.f}, {0.f, 0.f}};
    const float sc = 0.17677669529663687f * 1.4426950408889634f;

    for (int kc = 0; kc < 4; kc++) {
        float s[2][8][4];
#pragma unroll
        for (int mi = 0; mi < 2; mi++)
#pragma unroll
            for (int ni = 0; ni < 8; ni++)
#pragma unroll
                for (int r = 0; r < 4; r++) s[mi][ni][r] = 0.f;

#pragma unroll
        for (int nt = 0; nt < 4; nt++) {
            int keyrow = kc * 64 + nt * 16 + (lane & 15);
#pragma unroll
            for (int kt = 0; kt < 2; kt++) {
                uint32_t addr = sbK + keyrow * ATTN_ROWB + (kt * 2 + (lane >> 4)) * 16;
                uint32_t r0, r1, r2, r3;
                ldsm4(r0, r1, r2, r3, addr);
                uint32_t blo[2] = {r0, r2}, bhi[2] = {r1, r3};
#pragma unroll
                for (int mi = 0; mi < 2; mi++) {
                    mma16816(s[mi][nt * 2],     aq[mi][kt], blo);
                    mma16816(s[mi][nt * 2 + 1], aq[mi][kt], bhi);
                }
            }
        }

#pragma unroll
        for (int mi = 0; mi < 2; mi++)
#pragma unroll
            for (int ni = 0; ni < 8; ni++) {
                float p0 = exp2f(s[mi][ni][0] * sc);
                float p1 = exp2f(s[mi][ni][1] * sc);
                float p2 = exp2f(s[mi][ni][2] * sc);
                float p3 = exp2f(s[mi][ni][3] * sc);
                s[mi][ni][0] = p0; s[mi][ni][1] = p1;
                s[mi][ni][2] = p2; s[mi][ni][3] = p3;
                l[mi][0] += p0 + p1;
                l[mi][1] += p2 + p3;
            }

        uint32_t pa[2][4][4];
#pragma unroll
        for (int mi = 0; mi < 2; mi++)
#pragma unroll
            for (int kt = 0; kt < 4; kt++) {
                pa[mi][kt][0] = packh2(s[mi][kt * 2][0], s[mi][kt * 2][1]);
                pa[mi][kt][1] = packh2(s[mi][kt * 2][2], s[mi][kt * 2][3]);
                pa[mi][kt][2] = packh2(s[mi][kt * 2 + 1][0], s[mi][kt * 2 + 1][1]);
                pa[mi][kt][3] = packh2(s[mi][kt * 2 + 1][2], s[mi][kt * 2 + 1][3]);
            }

#pragma unroll
        for (int kt = 0; kt < 4; kt++) {
            int keyrow = kc * 64 + kt * 16 + (lane & 15);
#pragma unroll
            for (int dc = 0; dc < 2; dc++) {
                uint32_t addr = sbV + keyrow * ATTN_ROWB + (dc * 2 + (lane >> 4)) * 16;
                uint32_t r0, r1, r2, r3;
                ldsm4t(r0, r1, r2, r3, addr);
                uint32_t b0[2] = {r0, r1}, b1[2] = {r2, r3};
#pragma unroll
                for (int mi = 0; mi < 2; mi++) {
                    mma16816(o[mi][dc * 2],     pa[mi][kt], b0);
                    mma16816(o[mi][dc * 2 + 1], pa[mi][kt], b1);
                }
            }
        }
    }

#pragma unroll
    for (int mi = 0; mi < 2; mi++)
#pragma unroll
        for (int h = 0; h < 2; h++) {
            float v = l[mi][h];
            v += __shfl_xor_sync(0xffffffffu, v, 1);
            v += __shfl_xor_sync(0xffffffffu, v, 2);
            l[mi][h] = v;
        }

    int l4 = lane >> 2, l2 = (lane & 3) << 1;
#pragma unroll
    for (int mi = 0; mi < 2; mi++)
#pragma unroll
        for (int h = 0; h < 2; h++) {
            float inv = 1.f / l[mi][h];
            int row = wid * 32 + mi * 16 + l4 + h * 8;
            size_t ob = ((size_t)(win * 256 + row)) * 256 + head * 32;
#pragma unroll
            for (int ni = 0; ni < 4; ni++) {
                *(uint32_t*)(out + ob + ni * 8 + l2) =
                    packh2(o[mi][ni][h * 2] * inv, o[mi][ni][h * 2 + 1] * inv);
            }
        }
}

// ---------------------------------------------------------------------------
// Cross attention: 1 query x 16 keys, warp per head; fp16 Q and KV
// ---------------------------------------------------------------------------
__global__ void __launch_bounds__(256)
cross_attn_kernel(const __half* __restrict__ Q, const __half* __restrict__ KV,
                  __half* __restrict__ oh) {
    int g = blockIdx.x;
    int head = threadIdx.x >> 5, lane = threadIdx.x & 31;
    float qd = __half2float(Q[(size_t)g * 256 + head * 32 + lane]);
    size_t kvbase = (size_t)g * 16 * 512 + head * 32 + lane;
    const float sc = 0.17677669529663687f * 1.4426950408889634f;
    float s[16];
#pragma unroll
    for (int j = 0; j < 16; j++) {
        float p = qd * __half2float(KV[kvbase + (size_t)j * 512]);
#pragma unroll
        for (int o = 16; o; o >>= 1) p += __shfl_xor_sync(0xffffffffu, p, o);
        s[j] = p * sc;
    }
    float l = 0.f;
#pragma unroll
    for (int j = 0; j < 16; j++) { s[j] = exp2f(s[j]); l += s[j]; }
    float inv = 1.f / l, acc = 0.f;
#pragma unroll
    for (int j = 0; j < 16; j++)
        acc = fmaf(s[j], __half2float(KV[kvbase + 256 + (size_t)j * 512]), acc);
    oh[(size_t)g * 256 + head * 32 + lane] = __float2half(acc * inv);
}

// ---------------------------------------------------------------------------
// Host launch
// ---------------------------------------------------------------------------
extern "C" void kernel_launch(void* const* d_in, const int* in_sizes, int n_in,
                              void* d_out, int out_size) {
    const float* scale0 = (const float*)d_in[0];
    const float* scale1 = (const float*)d_in[1];
    const float* pe_w1  = (const float*)d_in[2];
    const float* pe_b1  = (const float*)d_in[3];
    const float* pe_w2  = (const float*)d_in[4];
    const float* ln1_g  = (const float*)d_in[5];
    const float* ln1_b  = (const float*)d_in[6];
    const float* wqkv   = (const float*)d_in[7];
    const float* bqkv   = (const float*)d_in[8];
    const float* wo     = (const float*)d_in[9];
    const float* bo     = (const float*)d_in[10];
    const float* ln2_g  = (const float*)d_in[11];
    const float* ln2_b  = (const float*)d_in[12];
    const float* mw1    = (const float*)d_in[13];
    const float* mb1    = (const float*)d_in[14];
    const float* mw2    = (const float*)d_in[15];
    const float* mb2    = (const float*)d_in[16];
    float* out = (float*)d_out;

    float* PE;
    __half *X0h, *X1h, *Gh, *Qbh, *QKVh, *QKVc, *A, *Ac, *H1, *H1c, *A3;
    __half *WqkvT, *WoT, *W1T, *W2T;
    cudaGetSymbolAddress((void**)&PE,   g_PE);
    cudaGetSymbolAddress((void**)&X0h,  g_X0h);
    cudaGetSymbolAddress((void**)&X1h,  g_X1h);
    cudaGetSymbolAddress((void**)&Gh,   g_Gh);
    cudaGetSymbolAddress((void**)&Qbh,  g_Qbh);
    cudaGetSymbolAddress((void**)&QKVh, g_QKVh);
    cudaGetSymbolAddress((void**)&QKVc, g_QKVc);
    cudaGetSymbolAddress((void**)&A,    g_A);
    cudaGetSymbolAddress((void**)&Ac,   g_Ac);
    cudaGetSymbolAddress((void**)&H1,   g_H1);
    cudaGetSymbolAddress((void**)&H1c,  g_H1c);
    cudaGetSymbolAddress((void**)&A3,   g_A3);
    cudaGetSymbolAddress((void**)&WqkvT, g_WqkvT);
    cudaGetSymbolAddress((void**)&WoT,   g_WoT);
    cudaGetSymbolAddress((void**)&W1T,   g_W1T);
    cudaGetSymbolAddress((void**)&W2T,   g_W2T);

    cudaFuncSetAttribute(attn_mma_kernel, cudaFuncAttributeMaxDynamicSharedMemorySize, ATTN_SMEM);
    cudaFuncSetAttribute(gemm_mma, cudaFuncAttributeMaxDynamicSharedMemorySize, GEMM_SMEM);

    // 0) weights (coalesced tile transpose) + position embeddings
    wconv_all_kernel<<<384, 256>>>(wqkv, wo, mw1, mw2, WqkvT, WoT, W1T, W2T);
    posemb_kernel<<<512, 256>>>(pe_w1, pe_b1, pe_w2, PE);

    // 1) inputs with fused LN1 (residual streams in fp16)
    add_pe0_ln_kernel<<<T0 / 8, 256>>>(scale0, PE, X0h, A, ln1_g, ln1_b);
    pool_add_ln_kernel<<<T1 / 8, 256>>>(scale1, PE, X0h, X1h, Ac,
                                        ln1_g + 256, ln1_b + 256);

    // 2) self-attention blocks, fine+coarse fused per launch (row-major QKV)
    gemm_mma<<<dim3(6, 512 + 32), 256, GEMM_SMEM>>>(
        A, WqkvT, bqkv, nullptr, nullptr, QKVh, 3,
        Ac, WqkvT + 196608, bqkv + 768, nullptr, nullptr, QKVc, 3,
        512, 256, 768, 768, 6);
    attn_mma_kernel<<<NWIN0 * 8 + NWIN1 * 8, 256, ATTN_SMEM>>>(
        QKVh, A, QKVc, Ac, NWIN0 * 8);
    gemm_mma<<<dim3(2, 512 + 32), 256, GEMM_SMEM>>>(
        A, WoT, bo, X0h, nullptr, X0h, 5,
        Ac, WoT + 65536, bo + 256, X1h, nullptr, X1h, 5,
        512, 256, 256, 256, 2);
    ln_half_h_kernel<<<T0 / 8 + T1 / 8, 256>>>(
        X0h, A, ln2_g, ln2_b, X1h, Ac, ln2_g + 256, ln2_b + 256, T0 / 8);
    gemm_mma<<<dim3(8, 512 + 32), 256, GEMM_SMEM>>>(
        A, W1T, mb1, nullptr, nullptr, H1, 1,
        Ac, W1T + 262144, mb1 + 1024, nullptr, nullptr, H1c, 1,
        512, 256, 1024, 1024, 8);
    // MLP2: fine -> out fp32 + fp16 copy into QKVh (epi 6); coarse -> X1h (epi 5)
    gemm_mma<<<dim3(2, 512 + 32), 256, GEMM_SMEM>>>(
        H1, W2T, mb2, X0h, out, QKVh, 6,
        H1c, W2T + 262144, mb2 + 256, X1h, nullptr, X1h, 5,
        512, 1024, 256, 256, 2);

    // 3) one2one cross-attention aggregation (scale-1 weights)
    // fine LN reads fp16 o0 copy (front [T0,256] region of QKVh)
    ln_pre_cross_kernel<<<T0 / 8 + T1 / 8, 256>>>(
        QKVh, A, X1h, Gh, A3, ln1_g + 256, ln1_b + 256, T0 / 8);
    // KV GEMM overwrites QKVh ([T0,512], epi 3) + fused Q GEMM (coarse)
    gemm_mma<<<dim3(4, 512 + 32), 256, GEMM_SMEM>>>(
        A, WqkvT + 196608 + 65536, bqkv + 768 + 256, nullptr, nullptr, QKVh, 3,
        A3, WqkvT + 196608, bqkv + 768, nullptr, nullptr, Qbh, 3,
        512, 256, 512, 256, 2);
    cross_attn_kernel<<<T1, 256>>>(Qbh, QKVh, A3);
    gemm_mma<<<dim3(2, 32), 256, GEMM_SMEM>>>(
        A3, WoT + 65536, bo + 256, Gh, nullptr, Gh, 5,
        A3, WoT + 65536, bo + 256, Gh, nullptr, Gh, 5, 32, 256, 256, 256, 2);
    ln_half_h_kernel<<<T1 / 8, 256>>>(
        Gh, A3, ln2_g + 256, ln2_b + 256,
        Gh, A3, ln2_g + 256, ln2_b + 256, T1 / 8);
    gemm_mma<<<dim3(8, 32), 256, GEMM_SMEM>>>(
        A3, W1T + 262144, mb1 + 1024, nullptr, nullptr, H1, 1,
        A3, W1T + 262144, mb1 + 1024, nullptr, nullptr, H1, 1, 32, 256, 1024, 1024, 8);
    gemm_mma<<<dim3(2, 32), 256, GEMM_SMEM>>>(
        H1, W2T + 262144, mb2 + 256, Gh, out + (size_t)NWIN0 * 256 * 256, nullptr, 4,
        H1, W2T + 262144, mb2 + 256, Gh, out + (size_t)NWIN0 * 256 * 256, nullptr, 4,
        32, 1024, 256, 256, 2);
}

// round 17
// speedup vs baseline: 1.0087x; 1.0087x over previous
#include <cuda_runtime.h>
#include <cuda_fp16.h>
#include <cstdint>
#include <cstddef>

// ---------------------------------------------------------------------------
// Dimensions: B=4, H=W=8, M=16, C=256, NH=8, HD=32, GW=2
// ---------------------------------------------------------------------------
#define T0      65536
#define T1      4096
#define NWIN0   256
#define NWIN1   16

#define TILE_BYTES 16384
#define BUF_BYTES  (2 * TILE_BYTES)
#define GEMM_SMEM  (3 * BUF_BYTES)

#define ATTN_ROWB  80
#define ATTN_SMEM  (3 * 256 * ATTN_ROWB)

// ---------------------------------------------------------------------------
// PTX helpers
// ---------------------------------------------------------------------------
__device__ __forceinline__ uint32_t smem_u32(const void* p) {
    uint32_t a;
    asm("{ .reg .u64 t; cvta.to.shared.u64 t, %1; cvt.u32.u64 %0, t; }" : "=r"(a) : "l"(p));
    return a;
}
__device__ __forceinline__ void cp16(uint32_t dst, const void* src) {
    asm volatile("cp.async.cg.shared.global [%0], [%1], 16;" :: "r"(dst), "l"(src) : "memory");
}
#define CP_COMMIT() asm volatile("cp.async.commit_group;" ::: "memory")
#define CP_WAIT2()  asm volatile("cp.async.wait_group 2;" ::: "memory")
#define CP_WAIT1()  asm volatile("cp.async.wait_group 1;" ::: "memory")
#define CP_WAIT0()  asm volatile("cp.async.wait_group 0;" ::: "memory")

__device__ __forceinline__ void ldsm4(uint32_t& r0, uint32_t& r1, uint32_t& r2,
                                      uint32_t& r3, uint32_t addr) {
    asm volatile("ldmatrix.sync.aligned.m8n8.x4.shared.b16 {%0,%1,%2,%3}, [%4];"
                 : "=r"(r0), "=r"(r1), "=r"(r2), "=r"(r3) : "r"(addr));
}
__device__ __forceinline__ void ldsm4t(uint32_t& r0, uint32_t& r1, uint32_t& r2,
                                       uint32_t& r3, uint32_t addr) {
    asm volatile("ldmatrix.sync.aligned.m8n8.x4.trans.shared.b16 {%0,%1,%2,%3}, [%4];"
                 : "=r"(r0), "=r"(r1), "=r"(r2), "=r"(r3) : "r"(addr));
}
__device__ __forceinline__ void mma16816(float* c, const uint32_t* a, const uint32_t* b) {
    asm volatile(
        "mma.sync.aligned.m16n8k16.row.col.f32.f16.f16.f32 "
        "{%0,%1,%2,%3}, {%4,%5,%6,%7}, {%8,%9}, {%0,%1,%2,%3};"
        : "+f"(c[0]), "+f"(c[1]), "+f"(c[2]), "+f"(c[3])
        : "r"(a[0]), "r"(a[1]), "r"(a[2]), "r"(a[3]), "r"(b[0]), "r"(b[1]));
}
__device__ __forceinline__ uint32_t packh2(float a, float b) {
    __half2 h = __floats2half2_rn(a, b);
    return *(uint32_t*)&h;
}
__device__ __forceinline__ float2 unpackh2(uint32_t u) {
    return __half22float2(*(__half2*)&u);
}

// Row-level permutation: gidx -> o1-row
__device__ __forceinline__ int scatter_perm(int g) {
    int rr = g & 15, r1 = rr >> 2, r2 = rr & 3;
    int bhw = g >> 4;
    int w = bhw & 7, h = (bhw >> 3) & 7, b = bhw >> 6;
    int R = h * 4 + r1, Cc = w * 4 + r2;
    return (((b * 2 + (R >> 4)) * 2 + (Cc >> 4)) << 8) + (R & 15) * 16 + (Cc & 15);
}

// ---------------------------------------------------------------------------
// Scratch (residual streams in fp16)
// ---------------------------------------------------------------------------
__device__ float g_PE [2 * 256 * 256];
__device__ __half g_X0h[(size_t)T0 * 256];
__device__ __half g_X1h[(size_t)T1 * 256];
__device__ __half g_Gh [(size_t)T1 * 256];
__device__ __half g_Qbh[(size_t)T1 * 256];
__device__ __half g_QKVh[(size_t)T0 * 768];
__device__ __half g_QKVc[(size_t)T1 * 768];
__device__ __half g_A  [(size_t)T0 * 256];
__device__ __half g_Ac [(size_t)T1 * 256];
__device__ __half g_H1 [(size_t)T0 * 1024];
__device__ __half g_H1c[(size_t)T1 * 1024];
__device__ __half g_A3 [(size_t)T1 * 256];
__device__ __half g_WqkvT[2 * 768 * 256];
__device__ __half g_WoT  [2 * 256 * 256];
__device__ __half g_W1T  [2 * 1024 * 256];
__device__ __half g_W2T  [2 * 256 * 1024];

// ---------------------------------------------------------------------------
// Elementwise helpers: contiguous 8 channels per lane
// ---------------------------------------------------------------------------
__device__ __forceinline__ void load8h(const __half* row, int lane,
                                       float4& v0, float4& v1) {
    uint4 u = ((const uint4*)row)[lane];
    float2 f0 = unpackh2(u.x), f1 = unpackh2(u.y);
    float2 f2 = unpackh2(u.z), f3 = unpackh2(u.w);
    v0 = make_float4(f0.x, f0.y, f1.x, f1.y);
    v1 = make_float4(f2.x, f2.y, f3.x, f3.y);
}
__device__ __forceinline__ void store8h(__half* row, int lane, float4 v0, float4 v1) {
    uint4 u;
    u.x = packh2(v0.x, v0.y); u.y = packh2(v0.z, v0.w);
    u.z = packh2(v1.x, v1.y); u.w = packh2(v1.z, v1.w);
    ((uint4*)row)[lane] = u;
}
__device__ __forceinline__ void ln_store8(float4 v0, float4 v1, int lane,
                                          const float* __restrict__ gamma,
                                          const float* __restrict__ beta,
                                          __half* __restrict__ orow) {
    float s = v0.x + v0.y + v0.z + v0.w + v1.x + v1.y + v1.z + v1.w;
#pragma unroll
    for (int d = 16; d; d >>= 1) s += __shfl_xor_sync(0xffffffffu, s, d);
    float mean = s * (1.f / 256.f);
    float d0x = v0.x - mean, d0y = v0.y - mean, d0z = v0.z - mean, d0w = v0.w - mean;
    float d1x = v1.x - mean, d1y = v1.y - mean, d1z = v1.z - mean, d1w = v1.w - mean;
    float q = d0x*d0x + d0y*d0y + d0z*d0z + d0w*d0w +
              d1x*d1x + d1y*d1y + d1z*d1z + d1w*d1w;
#pragma unroll
    for (int d = 16; d; d >>= 1) q += __shfl_xor_sync(0xffffffffu, q, d);
    float rstd = rsqrtf(q * (1.f / 256.f) + 1e-5f);
    float4 g0 = ((const float4*)gamma)[2 * lane], g1 = ((const float4*)gamma)[2 * lane + 1];
    float4 b0 = ((const float4*)beta)[2 * lane],  b1 = ((const float4*)beta)[2 * lane + 1];
    uint4 u;
    u.x = packh2(fmaf(d0x * rstd, g0.x, b0.x), fmaf(d0y * rstd, g0.y, b0.y));
    u.y = packh2(fmaf(d0z * rstd, g0.z, b0.z), fmaf(d0w * rstd, g0.w, b0.w));
    u.z = packh2(fmaf(d1x * rstd, g1.x, b1.x), fmaf(d1y * rstd, g1.y, b1.y));
    u.w = packh2(fmaf(d1z * rstd, g1.z, b1.z), fmaf(d1w * rstd, g1.w, b1.w));
    ((uint4*)orow)[lane] = u;
}

// ---------------------------------------------------------------------------
// Small kernels
// ---------------------------------------------------------------------------
__global__ void posemb_kernel(const float* __restrict__ pe_w1,
                              const float* __restrict__ pe_b1,
                              const float* __restrict__ pe_w2,
                              float* __restrict__ PE) {
    int s = blockIdx.x >> 8;
    int n = blockIdx.x & 255;
    int i = n >> 4, j = n & 15;
    float cy = (i - 8) * 0.125f;
    float cx = (j - 8) * 0.125f;
    __shared__ float hid[512];
    const float* w1 = pe_w1 + s * 2 * 512;
    const float* b1 = pe_b1 + s * 512;
    for (int k = threadIdx.x; k < 512; k += 256)
        hid[k] = fmaxf(0.f, fmaf(cy, w1[k], fmaf(cx, w1[512 + k], b1[k])));
    __syncthreads();
    const float* w2 = pe_w2 + (size_t)s * 512 * 256;
    int c = threadIdx.x;
    float acc = 0.f;
#pragma unroll 8
    for (int k = 0; k < 512; k++) acc = fmaf(hid[k], w2[(size_t)k * 256 + c], acc);
    PE[((size_t)s * 256 + n) * 256 + c] = acc;
}

__global__ void __launch_bounds__(256)
add_pe0_ln_kernel(const float* __restrict__ s0, const float* __restrict__ PE,
                  __half* __restrict__ X0h, __half* __restrict__ A,
                  const float* __restrict__ gamma, const float* __restrict__ beta) {
    int token = blockIdx.x * 8 + (threadIdx.x >> 5);
    int lane = threadIdx.x & 31;
    const float4* sr = (const float4*)(s0 + (size_t)token * 256);
    const float4* pr = (const float4*)(PE + (size_t)(token & 255) * 256);
    float4 v0 = sr[2 * lane], v1 = sr[2 * lane + 1];
    float4 p0 = pr[2 * lane], p1 = pr[2 * lane + 1];
    v0.x += p0.x; v0.y += p0.y; v0.z += p0.z; v0.w += p0.w;
    v1.x += p1.x; v1.y += p1.y; v1.z += p1.z; v1.w += p1.w;
    store8h(X0h + (size_t)token * 256, lane, v0, v1);
    ln_store8(v0, v1, lane, gamma, beta, A + (size_t)token * 256);
}

__global__ void __launch_bounds__(256)
pool_add_ln_kernel(const float* __restrict__ s1, const float* __restrict__ PE,
                   const __half* __restrict__ X0h, __half* __restrict__ X1h,
                   __half* __restrict__ Ac,
                   const float* __restrict__ gamma, const float* __restrict__ beta) {
    int token = blockIdx.x * 8 + (threadIdx.x >> 5);
    int lane = threadIdx.x & 31;
    int t  = token & 255;
    int gw = token >> 8;
    int b = gw >> 2, gi = (gw >> 1) & 1, gj = gw & 1;
    int ti = t >> 4, tj = t & 15;
    int R  = gi * 16 + ti, Cc = gj * 16 + tj;
    int h = R >> 2, r1 = R & 3, w = Cc >> 2, r2 = Cc & 3;
    int fw = b * 64 + h * 8 + w;
    float4 m0 = make_float4(-1e30f, -1e30f, -1e30f, -1e30f), m1 = m0;
#pragma unroll
    for (int p1 = 0; p1 < 4; p1++)
#pragma unroll
        for (int p2 = 0; p2 < 4; p2++) {
            int n = (r1 * 4 + p1) * 16 + r2 * 4 + p2;
            float4 a, c;
            load8h(X0h + ((size_t)fw * 256 + n) * 256, lane, a, c);
            m0.x = fmaxf(m0.x, a.x); m0.y = fmaxf(m0.y, a.y);
            m0.z = fmaxf(m0.z, a.z); m0.w = fmaxf(m0.w, a.w);
            m1.x = fmaxf(m1.x, c.x); m1.y = fmaxf(m1.y, c.y);
            m1.z = fmaxf(m1.z, c.z); m1.w = fmaxf(m1.w, c.w);
        }
    const float4* sr = (const float4*)(s1 + (size_t)token * 256);
    const float4* pr = (const float4*)(PE + (size_t)(256 + t) * 256);
    float4 s0v = sr[2 * lane], s1v = sr[2 * lane + 1];
    float4 p0 = pr[2 * lane], p1v = pr[2 * lane + 1];
    m0.x += s0v.x + p0.x; m0.y += s0v.y + p0.y;
    m0.z += s0v.z + p0.z; m0.w += s0v.w + p0.w;
    m1.x += s1v.x + p1v.x; m1.y += s1v.y + p1v.y;
    m1.z += s1v.z + p1v.z; m1.w += s1v.w + p1v.w;
    store8h(X1h + (size_t)token * 256, lane, m0, m1);
    ln_store8(m0, m1, lane, gamma, beta, Ac + (size_t)token * 256);
}

__global__ void __launch_bounds__(256)
ln_half_h_kernel(const __half* __restrict__ x, __half* __restrict__ o,
                 const float* __restrict__ gamma, const float* __restrict__ beta,
                 const __half* __restrict__ x2, __half* __restrict__ o2,
                 const float* __restrict__ gamma2, const float* __restrict__ beta2,
                 int split) {
    int blk = blockIdx.x;
    const __half* xp = x; __half* op = o;
    const float* gp = gamma; const float* bp = beta;
    if (blk >= split) { blk -= split; xp = x2; op = o2; gp = gamma2; bp = beta2; }
    int token = blk * 8 + (threadIdx.x >> 5);
    int lane = threadIdx.x & 31;
    float4 v0, v1;
    load8h(xp + (size_t)token * 256, lane, v0, v1);
    ln_store8(v0, v1, lane, gp, bp, op + (size_t)token * 256);
}

// Combined pre-cross LN; fine part reads fp32 o0.
__global__ void __launch_bounds__(256)
ln_pre_cross_kernel(const float* __restrict__ o0, __half* __restrict__ Afine,
                    const __half* __restrict__ X1h, __half* __restrict__ Gh,
                    __half* __restrict__ A3,
                    const float* __restrict__ gamma, const float* __restrict__ beta,
                    int split) {
    int blk = blockIdx.x;
    int lane = threadIdx.x & 31;
    if (blk < split) {
        int fidx = blk * 8 + (threadIdx.x >> 5);
        int pp = fidx & 15, p1 = pp >> 2, p2 = pp & 3;
        int grp = fidx >> 4;
        int rr = grp & 15, r1 = rr >> 2, r2 = rr & 3;
        int bhw = grp >> 4;
        int w = bhw & 7, h = (bhw >> 3) & 7, b = bhw >> 6;
        int fw = b * 64 + h * 8 + w;
        int n = (r1 * 4 + p1) * 16 + r2 * 4 + p2;
        const float4* xr = (const float4*)(o0 + ((size_t)fw * 256 + n) * 256);
        ln_store8(xr[2 * lane], xr[2 * lane + 1], lane, gamma, beta,
                  Afine + (size_t)fidx * 256);
    } else {
        int gidx = (blk - split) * 8 + (threadIdx.x >> 5);
        int rr = gidx & 15, r1 = rr >> 2, r2 = rr & 3;
        int bhw = gidx >> 4;
        int w = bhw & 7, h = (bhw >> 3) & 7, b = bhw >> 6;
        int R = h * 4 + r1, Cc = w * 4 + r2;
        int gi = R >> 4, ti = R & 15, gj = Cc >> 4, tj = Cc & 15;
        int win = (b * 2 + gi) * 2 + gj, tok = ti * 16 + tj;
        const __half* src = X1h + ((size_t)win * 256 + tok) * 256;
        uint4 raw = ((const uint4*)src)[lane];
        ((uint4*)(Gh + (size_t)gidx * 256))[lane] = raw;
        float4 v0, v1;
        load8h(src, lane, v0, v1);
        ln_store8(v0, v1, lane, gamma, beta, A3 + (size_t)gidx * 256);
    }
}

// Coalesced weight transpose-convert: W[K,N] fp32 -> T[N,K] fp16 (64x64 tiles)
__global__ void __launch_bounds__(256)
wconv_all_kernel(const float* __restrict__ wqkv, const float* __restrict__ wo,
                 const float* __restrict__ mw1, const float* __restrict__ mw2,
                 __half* __restrict__ Tqkv, __half* __restrict__ To,
                 __half* __restrict__ Tm1,  __half* __restrict__ Tm2) {
    __shared__ float sm[64][65];
    int bid = blockIdx.x;
    int s = bid / 192, r = bid % 192;
    const float* W; __half* T; int K, N, tk, tn;
    if (r < 48)      { W = wqkv + (size_t)s * 196608; T = Tqkv + (size_t)s * 196608;
                       K = 256;  N = 768;  tk = r % 4;          tn = r / 4; }
    else if (r < 64) { W = wo   + (size_t)s * 65536;  T = To   + (size_t)s * 65536;
                       K = 256;  N = 256;  tk = (r - 48) % 4;   tn = (r - 48) / 4; }
    else if (r < 128){ W = mw1  + (size_t)s * 262144; T = Tm1  + (size_t)s * 262144;
                       K = 256;  N = 1024; tk = (r - 64) % 4;   tn = (r - 64) / 4; }
    else             { W = mw2  + (size_t)s * 262144; T = Tm2  + (size_t)s * 262144;
                       K = 1024; N = 256;  tk = (r - 128) % 16; tn = (r - 128) / 16; }
    int k0 = tk * 64, n0 = tn * 64;
    int c = threadIdx.x & 63, rr = threadIdx.x >> 6;
#pragma unroll
    for (int i = 0; i < 16; i++) {
        int krow = rr + i * 4;
        sm[krow][c] = W[(size_t)(k0 + krow) * N + n0 + c];
    }
    __syncthreads();
#pragma unroll
    for (int i = 0; i < 16; i++) {
        int nrow = rr + i * 4;
        T[(size_t)(n0 + nrow) * K + k0 + c] = __float2half(sm[c][nrow]);
    }
}

// ---------------------------------------------------------------------------
// fp16 1-pass GEMM, dual-problem, runtime epilogue code per problem.
// epi 1: GELU -> Oh.  2: +resH -> Cp fp32.  3: -> Oh fp16.
// epi 4: +resH -> Cp fp32 @ scatter_perm.  5: +resH -> Oh fp16.
// ---------------------------------------------------------------------------
__global__ void __launch_bounds__(256)
gemm_mma(const __half* A, const __half* B,
         const float* bias, const __half* resH,
         float* Cp, __half* Oh, int epiA,
         const __half* A2, const __half* B2,
         const float* bias2, const __half* resH2,
         float* Cp2, __half* Oh2, int epiB,
         int bmSplit, int K, int ldc, int ldc2, int bn2Max) {
    extern __shared__ char smc[];
    const uint32_t sb = smem_u32(smc);
    int tid = threadIdx.x, lane = tid & 31, wid = tid >> 5;
    int wm = wid >> 2, wn = wid & 3;
    int bm = blockIdx.y, bn = blockIdx.x;
    int epi = epiA;
    if (bm >= bmSplit) {
        bm -= bmSplit;
        if (bn >= bn2Max) return;
        A = A2; B = B2; bias = bias2; resH = resH2; Cp = Cp2; Oh = Oh2;
        ldc = ldc2; epi = epiB;
    }

    const __half* src0 = A + (size_t)bm * 128 * K;
    const __half* src1 = B + (size_t)bn * 128 * K;

    int nc = K >> 6;
    int crow0 = tid >> 3, ccol = tid & 7;

#define PREFETCH(CH, BUF) do {                                                 \
    int _k0 = (CH) << 6;                                                       \
    const __half* _s[2] = {src0 + _k0, src1 + _k0};                            \
    _Pragma("unroll")                                                          \
    for (int _op = 0; _op < 2; _op++) {                                        \
        uint32_t _db = sb + (BUF) * BUF_BYTES + _op * TILE_BYTES;              \
        _Pragma("unroll")                                                      \
        for (int _i = 0; _i < 4; _i++) {                                       \
            int _row = crow0 + _i * 32;                                        \
            uint32_t _doff = _db + _row * 128 + ((ccol ^ (_row & 7)) << 4);    \
            cp16(_doff, _s[_op] + (size_t)_row * K + ccol * 8);                \
        }                                                                      \
    }                                                                          \
} while (0)

    float acc[4][4][4];
#pragma unroll
    for (int mi = 0; mi < 4; mi++)
#pragma unroll
        for (int ni = 0; ni < 4; ni++)
#pragma unroll
            for (int r = 0; r < 4; r++) acc[mi][ni][r] = 0.f;

    PREFETCH(0, 0);
    CP_COMMIT();
    if (nc > 1) { PREFETCH(1, 1); CP_COMMIT(); }

    int a_rl = lane & 15;
    int b_rl = ((lane >> 4) << 3) + (lane & 7);

    for (int ch = 0; ch < nc; ch++) {
        int buf = ch % 3;
        if (ch + 2 < nc) {
            PREFETCH(ch + 2, (ch + 2) % 3);
            CP_COMMIT();
            CP_WAIT2();
        } else if (ch + 1 < nc) {
            CP_WAIT1();
        } else {
            CP_WAIT0();
        }
        __syncthreads();

        uint32_t base = sb + buf * BUF_BYTES;
#pragma unroll
        for (int ks = 0; ks < 4; ks++) {
            uint32_t ah[4][4], bh[4][2];
            int achunk = ks * 2 + (lane >> 4);
            int bchunk = ks * 2 + ((lane >> 3) & 1);
#pragma unroll
            for (int mi = 0; mi < 4; mi++) {
                int row = wm * 64 + mi * 16 + a_rl;
                uint32_t off = (uint32_t)(row * 128 + ((achunk ^ (row & 7)) << 4));
                ldsm4(ah[mi][0], ah[mi][1], ah[mi][2], ah[mi][3], base + off);
            }
#pragma unroll
            for (int np = 0; np < 2; np++) {
                int row = wn * 32 + np * 16 + b_rl;
                uint32_t off = (uint32_t)(row * 128 + ((bchunk ^ (row & 7)) << 4));
                uint32_t r0, r1, r2, r3;
                ldsm4(r0, r1, r2, r3, base + TILE_BYTES + off);
                bh[np * 2][0] = r0; bh[np * 2][1] = r1;
                bh[np * 2 + 1][0] = r2; bh[np * 2 + 1][1] = r3;
            }
#pragma unroll
            for (int mi = 0; mi < 4; mi++)
#pragma unroll
                for (int ni = 0; ni < 4; ni++)
                    mma16816(acc[mi][ni], ah[mi], bh[ni]);
        }
        __syncthreads();
    }
#undef PREFETCH

    int l4 = lane >> 2, l2 = (lane & 3) << 1;
#pragma unroll
    for (int mi = 0; mi < 4; mi++) {
        int r0 = bm * 128 + wm * 64 + mi * 16 + l4;
        int sr0 = (epi == 4) ? scatter_perm(r0) : r0;
        int sr1 = (epi == 4) ? scatter_perm(r0 + 8) : r0 + 8;
#pragma unroll
        for (int ni = 0; ni < 4; ni++) {
            int cc = bn * 128 + wn * 32 + ni * 8 + l2;
            float b0 = bias[cc], b1 = bias[cc + 1];
            float v00 = acc[mi][ni][0] + b0, v01 = acc[mi][ni][1] + b1;
            float v10 = acc[mi][ni][2] + b0, v11 = acc[mi][ni][3] + b1;
            size_t o0 = (size_t)r0 * ldc + cc;
            size_t o1 = (size_t)(r0 + 8) * ldc + cc;
            if (epi == 1) {
                const float is2 = 0.7071067811865476f;
                float g00 = 0.5f * v00 * (1.f + erff(v00 * is2));
                float g01 = 0.5f * v01 * (1.f + erff(v01 * is2));
                float g10 = 0.5f * v10 * (1.f + erff(v10 * is2));
                float g11 = 0.5f * v11 * (1.f + erff(v11 * is2));
                *(uint32_t*)(Oh + o0) = packh2(g00, g01);
                *(uint32_t*)(Oh + o1) = packh2(g10, g11);
            } else if (epi == 3) {
                *(uint32_t*)(Oh + o0) = packh2(v00, v01);
                *(uint32_t*)(Oh + o1) = packh2(v10, v11);
            } else {
                float2 ra = unpackh2(*(const uint32_t*)(resH + o0));
                float2 rb = unpackh2(*(const uint32_t*)(resH + o1));
                v00 += ra.x; v01 += ra.y; v10 += rb.x; v11 += rb.y;
                if (epi == 5) {
                    *(uint32_t*)(Oh + o0) = packh2(v00, v01);
                    *(uint32_t*)(Oh + o1) = packh2(v10, v11);
                } else {
                    *(float2*)(Cp + (size_t)sr0 * ldc + cc) = make_float2(v00, v01);
                    *(float2*)(Cp + (size_t)sr1 * ldc + cc) = make_float2(v10, v11);
                }
            }
        }
    }
}

// ---------------------------------------------------------------------------
// Tensor-core flash attention (no-max softmax), dual-problem.
// QKV input row-major [T, 768].
// ---------------------------------------------------------------------------
__global__ void __launch_bounds__(256)
attn_mma_kernel(const __half* qkv, __half* out,
                const __half* qkv2, __half* out2, int ctaSplit) {
    extern __shared__ char smc[];
    const uint32_t sb = smem_u32(smc);
    const uint32_t sbQ = sb, sbK = sb + 256 * ATTN_ROWB, sbV = sb + 512 * ATTN_ROWB;
    int cta = blockIdx.x;
    if (cta >= ctaSplit) { cta -= ctaSplit; qkv = qkv2; out = out2; }
    int win = cta >> 3, head = cta & 7;
    int tid = threadIdx.x, lane = tid & 31, wid = tid >> 5;

    {
        const uint4* src = (const uint4*)(qkv + ((size_t)(win * 256 + tid) * 768 + head * 32));
        uint4* dq = (uint4*)(smc + tid * ATTN_ROWB);
        uint4* dk = (uint4*)(smc + 256 * ATTN_ROWB + tid * ATTN_ROWB);
        uint4* dv = (uint4*)(smc + 512 * ATTN_ROWB + tid * ATTN_ROWB);
#pragma unroll
        for (int c = 0; c < 4; c++) dq[c] = src[c];
#pragma unroll
        for (int c = 0; c < 4; c++) dk[c] = src[32 + c];
#pragma unroll
        for (int c = 0; c < 4; c++) dv[c] = src[64 + c];
    }
    __syncthreads();

    uint32_t aq[2][2][4];
#pragma unroll
    for (int mi = 0; mi < 2; mi++)
#pragma unroll
        for (int kt = 0; kt < 2; kt++) {
            int row = wid * 32 + mi * 16 + (lane & 15);
            uint32_t addr = sbQ + row * ATTN_ROWB + (kt * 2 + (lane >> 4)) * 16;
            ldsm4(aq[mi][kt][0], aq[mi][kt][1], aq[mi][kt][2], aq[mi][kt][3], addr);
        }

    float o[2][4][4];
#pragma unroll
    for (int mi = 0; mi < 2; mi++)
#pragma unroll
        for (int ni = 0; ni < 4; ni++)
#pragma unroll
            for (int r = 0; r < 4; r++) o[mi][ni][r] = 0.f;
    float l[2][2] = {{0.f, 0.f}, {0.f, 0.f}};
    const float sc = 0.17677669529663687f * 1.4426950408889634f;

    for (int kc = 0; kc < 4; kc++) {
        float s[2][8][4];
#pragma unroll
        for (int mi = 0; mi < 2; mi++)
#pragma unroll
            for (int ni = 0; ni < 8; ni++)
#pragma unroll
                for (int r = 0; r < 4; r++) s[mi][ni][r] = 0.f;

#pragma unroll
        for (int nt = 0; nt < 4; nt++) {
            int keyrow = kc * 64 + nt * 16 + (lane & 15);
#pragma unroll
            for (int kt = 0; kt < 2; kt++) {
                uint32_t addr = sbK + keyrow * ATTN_ROWB + (kt * 2 + (lane >> 4)) * 16;
                uint32_t r0, r1, r2, r3;
                ldsm4(r0, r1, r2, r3, addr);
                uint32_t blo[2] = {r0, r2}, bhi[2] = {r1, r3};
#pragma unroll
                for (int mi = 0; mi < 2; mi++) {
                    mma16816(s[mi][nt * 2],     aq[mi][kt], blo);
                    mma16816(s[mi][nt * 2 + 1], aq[mi][kt], bhi);
                }
            }
        }

#pragma unroll
        for (int mi = 0; mi < 2; mi++)
#pragma unroll
            for (int ni = 0; ni < 8; ni++) {
                float p0 = exp2f(s[mi][ni][0] * sc);
                float p1 = exp2f(s[mi][ni][1] * sc);
                float p2 = exp2f(s[mi][ni][2] * sc);
                float p3 = exp2f(s[mi][ni][3] * sc);
                s[mi][ni][0] = p0; s[mi][ni][1] = p1;
                s[mi][ni][2] = p2; s[mi][ni][3] = p3;
                l[mi][0] += p0 + p1;
                l[mi][1] += p2 + p3;
            }

        uint32_t pa[2][4][4];
#pragma unroll
        for (int mi = 0; mi < 2; mi++)
#pragma unroll
            for (int kt = 0; kt < 4; kt++) {
                pa[mi][kt][0] = packh2(s[mi][kt * 2][0], s[mi][kt * 2][1]);
                pa[mi][kt][1] = packh2(s[mi][kt * 2][2], s[mi][kt * 2][3]);
                pa[mi][kt][2] = packh2(s[mi][kt * 2 + 1][0], s[mi][kt * 2 + 1][1]);
                pa[mi][kt][3] = packh2(s[mi][kt * 2 + 1][2], s[mi][kt * 2 + 1][3]);
            }

#pragma unroll
        for (int kt = 0; kt < 4; kt++) {
            int keyrow = kc * 64 + kt * 16 + (lane & 15);
#pragma unroll
            for (int dc = 0; dc < 2; dc++) {
                uint32_t addr = sbV + keyrow * ATTN_ROWB + (dc * 2 + (lane >> 4)) * 16;
                uint32_t r0, r1, r2, r3;
                ldsm4t(r0, r1, r2, r3, addr);
                uint32_t b0[2] = {r0, r1}, b1[2] = {r2, r3};
#pragma unroll
                for (int mi = 0; mi < 2; mi++) {
                    mma16816(o[mi][dc * 2],     pa[mi][kt], b0);
                    mma16816(o[mi][dc * 2 + 1], pa[mi][kt], b1);
                }
            }
        }
    }

#pragma unroll
    for (int mi = 0; mi < 2; mi++)
#pragma unroll
        for (int h = 0; h < 2; h++) {
            float v = l[mi][h];
            v += __shfl_xor_sync(0xffffffffu, v, 1);
            v += __shfl_xor_sync(0xffffffffu, v, 2);
            l[mi][h] = v;
        }

    int l4 = lane >> 2, l2 = (lane & 3) << 1;
#pragma unroll
    for (int mi = 0; mi < 2; mi++)
#pragma unroll
        for (int h = 0; h < 2; h++) {
            float inv = 1.f / l[mi][h];
            int row = wid * 32 + mi * 16 + l4 + h * 8;
            size_t ob = ((size_t)(win * 256 + row)) * 256 + head * 32;
#pragma unroll
            for (int ni = 0; ni < 4; ni++) {
                *(uint32_t*)(out + ob + ni * 8 + l2) =
                    packh2(o[mi][ni][h * 2] * inv, o[mi][ni][h * 2 + 1] * inv);
            }
        }
}

// ---------------------------------------------------------------------------
// Cross attention: 1 query x 16 keys, warp per head; fp16 Q and KV
// ---------------------------------------------------------------------------
__global__ void __launch_bounds__(256)
cross_attn_kernel(const __half* __restrict__ Q, const __half* __restrict__ KV,
                  __half* __restrict__ oh) {
    int g = blockIdx.x;
    int head = threadIdx.x >> 5, lane = threadIdx.x & 31;
    float qd = __half2float(Q[(size_t)g * 256 + head * 32 + lane]);
    size_t kvbase = (size_t)g * 16 * 512 + head * 32 + lane;
    const float sc = 0.17677669529663687f * 1.4426950408889634f;
    float s[16];
#pragma unroll
    for (int j = 0; j < 16; j++) {
        float p = qd * __half2float(KV[kvbase + (size_t)j * 512]);
#pragma unroll
        for (int o = 16; o; o >>= 1) p += __shfl_xor_sync(0xffffffffu, p, o);
        s[j] = p * sc;
    }
    float l = 0.f;
#pragma unroll
    for (int j = 0; j < 16; j++) { s[j] = exp2f(s[j]); l += s[j]; }
    float inv = 1.f / l, acc = 0.f;
#pragma unroll
    for (int j = 0; j < 16; j++)
        acc = fmaf(s[j], __half2float(KV[kvbase + 256 + (size_t)j * 512]), acc);
    oh[(size_t)g * 256 + head * 32 + lane] = __float2half(acc * inv);
}

// ---------------------------------------------------------------------------
// Host launch
// ---------------------------------------------------------------------------
extern "C" void kernel_launch(void* const* d_in, const int* in_sizes, int n_in,
                              void* d_out, int out_size) {
    const float* scale0 = (const float*)d_in[0];
    const float* scale1 = (const float*)d_in[1];
    const float* pe_w1  = (const float*)d_in[2];
    const float* pe_b1  = (const float*)d_in[3];
    const float* pe_w2  = (const float*)d_in[4];
    const float* ln1_g  = (const float*)d_in[5];
    const float* ln1_b  = (const float*)d_in[6];
    const float* wqkv   = (const float*)d_in[7];
    const float* bqkv   = (const float*)d_in[8];
    const float* wo     = (const float*)d_in[9];
    const float* bo     = (const float*)d_in[10];
    const float* ln2_g  = (const float*)d_in[11];
    const float* ln2_b  = (const float*)d_in[12];
    const float* mw1    = (const float*)d_in[13];
    const float* mb1    = (const float*)d_in[14];
    const float* mw2    = (const float*)d_in[15];
    const float* mb2    = (const float*)d_in[16];
    float* out = (float*)d_out;

    float* PE;
    __half *X0h, *X1h, *Gh, *Qbh, *QKVh, *QKVc, *A, *Ac, *H1, *H1c, *A3;
    __half *WqkvT, *WoT, *W1T, *W2T;
    cudaGetSymbolAddress((void**)&PE,   g_PE);
    cudaGetSymbolAddress((void**)&X0h,  g_X0h);
    cudaGetSymbolAddress((void**)&X1h,  g_X1h);
    cudaGetSymbolAddress((void**)&Gh,   g_Gh);
    cudaGetSymbolAddress((void**)&Qbh,  g_Qbh);
    cudaGetSymbolAddress((void**)&QKVh, g_QKVh);
    cudaGetSymbolAddress((void**)&QKVc, g_QKVc);
    cudaGetSymbolAddress((void**)&A,    g_A);
    cudaGetSymbolAddress((void**)&Ac,   g_Ac);
    cudaGetSymbolAddress((void**)&H1,   g_H1);
    cudaGetSymbolAddress((void**)&H1c,  g_H1c);
    cudaGetSymbolAddress((void**)&A3,   g_A3);
    cudaGetSymbolAddress((void**)&WqkvT, g_WqkvT);
    cudaGetSymbolAddress((void**)&WoT,   g_WoT);
    cudaGetSymbolAddress((void**)&W1T,   g_W1T);
    cudaGetSymbolAddress((void**)&W2T,   g_W2T);

    cudaFuncSetAttribute(attn_mma_kernel, cudaFuncAttributeMaxDynamicSharedMemorySize, ATTN_SMEM);
    cudaFuncSetAttribute(gemm_mma, cudaFuncAttributeMaxDynamicSharedMemorySize, GEMM_SMEM);

    // 0) weights (coalesced tile transpose) + position embeddings
    wconv_all_kernel<<<384, 256>>>(wqkv, wo, mw1, mw2, WqkvT, WoT, W1T, W2T);
    posemb_kernel<<<512, 256>>>(pe_w1, pe_b1, pe_w2, PE);

    // 1) inputs with fused LN1 (residual streams in fp16)
    add_pe0_ln_kernel<<<T0 / 8, 256>>>(scale0, PE, X0h, A, ln1_g, ln1_b);
    pool_add_ln_kernel<<<T1 / 8, 256>>>(scale1, PE, X0h, X1h, Ac,
                                        ln1_g + 256, ln1_b + 256);

    // 2) self-attention blocks, fine+coarse fused per launch
    gemm_mma<<<dim3(6, 512 + 32), 256, GEMM_SMEM>>>(
        A, WqkvT, bqkv, nullptr, nullptr, QKVh, 3,
        Ac, WqkvT + 196608, bqkv + 768, nullptr, nullptr, QKVc, 3,
        512, 256, 768, 768, 6);
    attn_mma_kernel<<<NWIN0 * 8 + NWIN1 * 8, 256, ATTN_SMEM>>>(
        QKVh, A, QKVc, Ac, NWIN0 * 8);
    gemm_mma<<<dim3(2, 512 + 32), 256, GEMM_SMEM>>>(
        A, WoT, bo, X0h, nullptr, X0h, 5,
        Ac, WoT + 65536, bo + 256, X1h, nullptr, X1h, 5,
        512, 256, 256, 256, 2);
    ln_half_h_kernel<<<T0 / 8 + T1 / 8, 256>>>(
        X0h, A, ln2_g, ln2_b, X1h, Ac, ln2_g + 256, ln2_b + 256, T0 / 8);
    gemm_mma<<<dim3(8, 512 + 32), 256, GEMM_SMEM>>>(
        A, W1T, mb1, nullptr, nullptr, H1, 1,
        Ac, W1T + 262144, mb1 + 1024, nullptr, nullptr, H1c, 1,
        512, 256, 1024, 1024, 8);
    // MLP2: fine -> out (fp32, epi2), coarse -> X1h (fp16, epi5)
    gemm_mma<<<dim3(2, 512 + 32), 256, GEMM_SMEM>>>(
        H1, W2T, mb2, X0h, out, nullptr, 2,
        H1c, W2T + 262144, mb2 + 256, X1h, nullptr, X1h, 5,
        512, 1024, 256, 256, 2);

    // 3) one2one cross-attention aggregation (scale-1 weights)
    ln_pre_cross_kernel<<<T0 / 8 + T1 / 8, 256>>>(
        out, A, X1h, Gh, A3, ln1_g + 256, ln1_b + 256, T0 / 8);
    gemm_mma<<<dim3(4, 512 + 32), 256, GEMM_SMEM>>>(
        A, WqkvT + 196608 + 65536, bqkv + 768 + 256, nullptr, nullptr, QKVh, 3,
        A3, WqkvT + 196608, bqkv + 768, nullptr, nullptr, Qbh, 3,
        512, 256, 512, 256, 2);
    cross_attn_kernel<<<T1, 256>>>(Qbh, QKVh, A3);
    gemm_mma<<<dim3(2, 32), 256, GEMM_SMEM>>>(
        A3, WoT + 65536, bo + 256, Gh, nullptr, Gh, 5,
        A3, WoT + 65536, bo + 256, Gh, nullptr, Gh, 5, 32, 256, 256, 256, 2);
    ln_half_h_kernel<<<T1 / 8, 256>>>(
        Gh, A3, ln2_g + 256, ln2_b + 256,
        Gh, A3, ln2_g + 256, ln2_b + 256, T1 / 8);
    gemm_mma<<<dim3(8, 32), 256, GEMM_SMEM>>>(
        A3, W1T + 262144, mb1 + 1024, nullptr, nullptr, H1, 1,
        A3, W1T + 262144, mb1 + 1024, nullptr, nullptr, H1, 1, 32, 256, 1024, 1024, 8);
    gemm_mma<<<dim3(2, 32), 256, GEMM_SMEM>>>(
        H1, W2T + 262144, mb2 + 256, Gh, out + (size_t)NWIN0 * 256 * 256, nullptr, 4,
        H1, W2T + 262144, mb2 + 256, Gh, out + (size_t)NWIN0 * 256 * 256, nullptr, 4,
        32, 1024, 256, 256, 2);
}